// round 14
// baseline (speedup 1.0000x reference)
#include <cuda_runtime.h>
#include <cuda_fp16.h>
#include <stdint.h>

#define B_  2
#define N_  2048
#define C_  512
#define H_  8
#define HD  64
#define BN_ (B_*N_)
#define BH_ (B_*H_)
#define SCALE 0.04419417382415922f

__device__ __half g_xn[(size_t)BN_ * C_];
__device__ __half g_q [(size_t)BH_ * N_ * HD];
__device__ __half g_k [(size_t)BH_ * N_ * HD];
__device__ __half g_v [(size_t)BH_ * N_ * HD];   // [b,h,d,n] transposed
__device__ __half g_ao[(size_t)BH_ * N_ * HD];
__device__ __half g_wt[4][(size_t)C_ * C_];      // transposed [n][k]

__device__ __forceinline__ void mma_f16(float c[4],
    uint32_t a0, uint32_t a1, uint32_t a2, uint32_t a3, uint32_t b0, uint32_t b1)
{
    asm volatile(
        "mma.sync.aligned.m16n8k16.row.col.f32.f16.f16.f32 "
        "{%0,%1,%2,%3}, {%4,%5,%6,%7}, {%8,%9}, {%0,%1,%2,%3};"
        : "+f"(c[0]), "+f"(c[1]), "+f"(c[2]), "+f"(c[3])
        : "r"(a0), "r"(a1), "r"(a2), "r"(a3), "r"(b0), "r"(b1));
}
__device__ __forceinline__ void ldsm4(uint32_t& r0, uint32_t& r1, uint32_t& r2,
                                      uint32_t& r3, uint32_t a)
{
    asm volatile("ldmatrix.sync.aligned.m8n8.x4.shared.b16 {%0,%1,%2,%3}, [%4];"
        : "=r"(r0), "=r"(r1), "=r"(r2), "=r"(r3) : "r"(a));
}
__device__ __forceinline__ void cp16(uint32_t dst, const void* src) {
    asm volatile("cp.async.cg.shared.global [%0], [%1], 16;" :: "r"(dst), "l"(src));
}
#define CPCOMMIT() asm volatile("cp.async.commit_group;")
#define CPWAIT0()  asm volatile("cp.async.wait_group 0;")

// ---------------- weight prep ---------------------------------------------------
__global__ __launch_bounds__(256) void prep_w(
    const float* __restrict__ wq, const float* __restrict__ wk,
    const float* __restrict__ wv, const float* __restrict__ wo)
{
    __shared__ float tile[32][33];
    int m = blockIdx.z;
    const float* s = (m == 0) ? wq : (m == 1) ? wk : (m == 2) ? wv : wo;
    int x0 = blockIdx.x * 32, y0 = blockIdx.y * 32;
    int tx = threadIdx.x & 31, ty = threadIdx.x >> 5;
    #pragma unroll
    for (int i = 0; i < 4; i++)
        tile[ty + 8 * i][tx] = s[(size_t)(y0 + ty + 8 * i) * C_ + x0 + tx];
    __syncthreads();
    #pragma unroll
    for (int i = 0; i < 4; i++)
        g_wt[m][(size_t)(x0 + ty + 8 * i) * C_ + y0 + tx] = __float2half_rn(tile[tx][ty + 8 * i]);
}

// ---------------- LayerNorm (fp16 output) ---------------------------------------
__global__ __launch_bounds__(128) void ln_kernel(
    const float* __restrict__ x, const float* __restrict__ g,
    const float* __restrict__ bta, __half* __restrict__ xn)
{
    int row = blockIdx.x, tid = threadIdx.x;
    float4 v = reinterpret_cast<const float4*>(x + (size_t)row * C_)[tid];
    float s = v.x + v.y + v.z + v.w;
    float ss = v.x*v.x + v.y*v.y + v.z*v.z + v.w*v.w;
    #pragma unroll
    for (int o = 16; o; o >>= 1) {
        s  += __shfl_xor_sync(~0u, s,  o);
        ss += __shfl_xor_sync(~0u, ss, o);
    }
    __shared__ float sh[8];
    int w = tid >> 5, l = tid & 31;
    if (l == 0) { sh[w] = s; sh[4 + w] = ss; }
    __syncthreads();
    float st = sh[0]+sh[1]+sh[2]+sh[3], sst = sh[4]+sh[5]+sh[6]+sh[7];
    float mean = st * (1.0f / C_);
    float var  = sst * (1.0f / C_) - mean * mean;
    float r = rsqrtf(var + 1e-5f);
    float4 gg = reinterpret_cast<const float4*>(g)[tid];
    float4 bb = reinterpret_cast<const float4*>(bta)[tid];
    __half2 h0 = __floats2half2_rn((v.x - mean) * r * gg.x + bb.x,
                                   (v.y - mean) * r * gg.y + bb.y);
    __half2 h1 = __floats2half2_rn((v.z - mean) * r * gg.z + bb.z,
                                   (v.w - mean) * r * gg.w + bb.w);
    uint2 st2 = make_uint2(*reinterpret_cast<uint32_t*>(&h0),
                           *reinterpret_cast<uint32_t*>(&h1));
    *reinterpret_cast<uint2*>(xn + (size_t)row * C_ + tid * 4) = st2;
}

// ============================================================================
// fp16 GEMM (round-13 verified): 64x64 tile, BK=64, 128 thr, stride-144 smem.
// ============================================================================
__device__ __forceinline__ void gemm_frag_f16(
    uint32_t aBase, uint32_t bBase, int buf, int wM, int wN,
    uint32_t ofA, uint32_t ofB, float acc[2][4][4])
{
    #pragma unroll
    for (int ks = 0; ks < 4; ks++) {
        uint32_t a[2][4];
        #pragma unroll
        for (int mf = 0; mf < 2; mf++)
            ldsm4(a[mf][0], a[mf][1], a[mf][2], a[mf][3],
                  aBase + (uint32_t)(buf * 9216 + (wM * 32 + mf * 16) * 144 + ks * 32) + ofA);
        #pragma unroll
        for (int p = 0; p < 2; p++) {
            uint32_t b0, b1, b2, b3;
            ldsm4(b0, b1, b2, b3,
                  bBase + (uint32_t)(buf * 9216 + (wN * 32 + p * 16) * 144 + ks * 32) + ofB);
            #pragma unroll
            for (int mf = 0; mf < 2; mf++) {
                mma_f16(acc[mf][2*p],   a[mf][0], a[mf][1], a[mf][2], a[mf][3], b0, b1);
                mma_f16(acc[mf][2*p+1], a[mf][0], a[mf][1], a[mf][2], a[mf][3], b2, b3);
            }
        }
    }
}

__global__ __launch_bounds__(128) void qkv_gemm(
    const __half* __restrict__ A,
    const float* __restrict__ bq, const float* __restrict__ bk, const float* __restrict__ bv,
    __half* __restrict__ Q, __half* __restrict__ K, __half* __restrict__ V)
{
    __shared__ __align__(16) char sAc[2 * 9216];
    __shared__ __align__(16) char sBc[2 * 9216];
    uint32_t aB = (uint32_t)__cvta_generic_to_shared(sAc);
    uint32_t bB = (uint32_t)__cvta_generic_to_shared(sBc);

    int z = blockIdx.z;
    const __half* Wt = &g_wt[z][0];
    const float* bias = (z == 0) ? bq : (z == 1) ? bk : bv;

    int tid = threadIdx.x, lane = tid & 31, wid = tid >> 5;
    int wM = wid >> 1, wN = wid & 1, g = lane >> 2, c = lane & 3;
    int rowbase = blockIdx.y * 64, colbase = blockIdx.x * 64;

    int sel = lane >> 3, l8 = lane & 7;
    uint32_t ofA = (uint32_t)(((sel & 1) * 8 + l8) * 144 + (sel >> 1) * 16);
    uint32_t ofB = (uint32_t)(((sel >> 1) * 8 + l8) * 144 + (sel & 1) * 16);

    #pragma unroll
    for (int p = 0; p < 4; p++) {
        int idx = tid + p * 128;
        int r = idx >> 3, k8 = idx & 7;
        uint32_t off = (uint32_t)(r * 144 + k8 * 16);
        cp16(aB + off, A  + (size_t)(rowbase + r) * C_ + k8 * 8);
        cp16(bB + off, Wt + (size_t)(colbase + r) * C_ + k8 * 8);
    }
    CPCOMMIT();

    float acc[2][4][4] = {};
    for (int t = 0; t < 8; t++) {
        int buf = t & 1;
        CPWAIT0();
        __syncthreads();
        if (t < 7) {
            int k0 = (t + 1) * 64;
            uint32_t bo = (uint32_t)((buf ^ 1) * 9216);
            #pragma unroll
            for (int p = 0; p < 4; p++) {
                int idx = tid + p * 128;
                int r = idx >> 3, k8 = idx & 7;
                uint32_t off = bo + (uint32_t)(r * 144 + k8 * 16);
                cp16(aB + off, A  + (size_t)(rowbase + r) * C_ + k0 + k8 * 8);
                cp16(bB + off, Wt + (size_t)(colbase + r) * C_ + k0 + k8 * 8);
            }
            CPCOMMIT();
        }
        gemm_frag_f16(aB, bB, buf, wM, wN, ofA, ofB, acc);
    }

    int h = blockIdx.x;
    int bb = rowbase >> 11, nbase = rowbase & (N_ - 1);
    if (z != 2) {
        __half* out = z ? K : Q;
        float sc = z ? 1.0f : SCALE;
        #pragma unroll
        for (int mf = 0; mf < 2; mf++) {
            int rl = wM * 32 + mf * 16 + g;
            #pragma unroll
            for (int nf = 0; nf < 4; nf++) {
                int d = wN * 32 + nf * 8 + 2 * c;
                float b0 = bias[colbase + d], b1 = bias[colbase + d + 1];
                __half2 h0 = __floats2half2_rn((acc[mf][nf][0] + b0) * sc,
                                               (acc[mf][nf][1] + b1) * sc);
                __half2 h1 = __floats2half2_rn((acc[mf][nf][2] + b0) * sc,
                                               (acc[mf][nf][3] + b1) * sc);
                *reinterpret_cast<__half2*>(
                    out + (((size_t)bb * H_ + h) * N_ + nbase + rl) * HD + d) = h0;
                *reinterpret_cast<__half2*>(
                    out + (((size_t)bb * H_ + h) * N_ + nbase + rl + 8) * HD + d) = h1;
            }
        }
    } else {
        __syncthreads();
        float* tb = (float*)sAc;   // [64][65]
        #pragma unroll
        for (int mf = 0; mf < 2; mf++) {
            int rl = wM * 32 + mf * 16 + g;
            #pragma unroll
            for (int nf = 0; nf < 4; nf++) {
                int d = wN * 32 + nf * 8 + 2 * c;
                float b0 = bias[colbase + d], b1 = bias[colbase + d + 1];
                tb[d * 65 + rl]           = acc[mf][nf][0] + b0;
                tb[(d + 1) * 65 + rl]     = acc[mf][nf][1] + b1;
                tb[d * 65 + rl + 8]       = acc[mf][nf][2] + b0;
                tb[(d + 1) * 65 + rl + 8] = acc[mf][nf][3] + b1;
            }
        }
        __syncthreads();
        #pragma unroll
        for (int p = 0; p < 8; p++) {
            int idx = tid + p * 128;
            int d = idx >> 4, n4 = idx & 15;
            __half2 v0 = __floats2half2_rn(tb[d * 65 + n4 * 4],     tb[d * 65 + n4 * 4 + 1]);
            __half2 v1 = __floats2half2_rn(tb[d * 65 + n4 * 4 + 2], tb[d * 65 + n4 * 4 + 3]);
            uint2 st = make_uint2(*reinterpret_cast<uint32_t*>(&v0),
                                  *reinterpret_cast<uint32_t*>(&v1));
            *reinterpret_cast<uint2*>(
                V + (((size_t)bb * H_ + h) * HD + d) * N_ + nbase + n4 * 4) = st;
        }
    }
}

// ============================================================================
// Flash attention fp16, software-pipelined: PV(t) interleaved with QK(t+1).
// 128 q/CTA, 4 warps x 32 q-rows. smem layout identical to round 13.
// ============================================================================
#define AKSB(buf) ((buf) * 9216)
#define AVSB(buf) (18432 + (buf) * 9216)
#define APSB      36864
#define AMSB      55296
#define ATTN_SMB  55808

__global__ __launch_bounds__(128, 2) void attn_t(
    const __half* __restrict__ Q, const __half* __restrict__ K,
    const __half* __restrict__ Vt, const int* __restrict__ mask,
    __half* __restrict__ O)
{
    extern __shared__ char smc[];
    float* ms = (float*)(smc + AMSB);
    uint32_t sb = (uint32_t)__cvta_generic_to_shared(smc);

    int bh = blockIdx.y, b = bh >> 3;
    int qbase = blockIdx.x * 128;
    int tid = threadIdx.x, wid = tid >> 5, lane = tid & 31;
    int g = lane >> 2, c = lane & 3;
    int r0 = qbase + wid * 32 + g;
    const size_t kvb = (size_t)bh * N_ * HD;

    int sel = lane >> 3, l8 = lane & 7;
    uint32_t ofB = (uint32_t)(((sel >> 1) * 8 + l8) * 144 + (sel & 1) * 16);
    uint32_t ofA = (uint32_t)(((sel & 1) * 8 + l8) * 144 + (sel >> 1) * 16);
    uint32_t pbase = sb + (uint32_t)(APSB + wid * 4608) + ofA;

    uint32_t qf[2][4][4];
    #pragma unroll
    for (int mf = 0; mf < 2; mf++) {
        const uint32_t* Qp = reinterpret_cast<const uint32_t*>(
            Q + ((size_t)bh * N_ + r0 + 16 * mf) * HD);
        #pragma unroll
        for (int ks = 0; ks < 4; ks++) {
            qf[mf][ks][0] = Qp[ks * 8 + c];
            qf[mf][ks][1] = Qp[256 + ks * 8 + c];
            qf[mf][ks][2] = Qp[ks * 8 + 4 + c];
            qf[mf][ks][3] = Qp[256 + ks * 8 + 4 + c];
        }
    }

    // tile 0 -> buf0
    #pragma unroll
    for (int p = 0; p < 4; p++) {
        int idx = tid + p * 128;
        int key = idx >> 3, d8 = idx & 7;
        cp16(sb + (uint32_t)(AKSB(0) + key * 144 + d8 * 16),
             K + kvb + (size_t)key * HD + d8 * 8);
    }
    #pragma unroll
    for (int p = 0; p < 4; p++) {
        int idx = tid + p * 128;
        int d = idx >> 3, k8 = idx & 7;
        cp16(sb + (uint32_t)(AVSB(0) + d * 144 + k8 * 16),
             Vt + kvb + (size_t)d * N_ + k8 * 8);
    }
    CPCOMMIT();
    if (tid < 64) ms[tid] = mask[b * N_ + tid] ? 0.0f : -10000.0f;
    CPWAIT0();
    __syncthreads();

    // issue tile 1 -> buf1 (overlaps QK(0))
    #pragma unroll
    for (int p = 0; p < 4; p++) {
        int idx = tid + p * 128;
        int key = idx >> 3, d8 = idx & 7;
        cp16(sb + (uint32_t)(AKSB(1) + key * 144 + d8 * 16),
             K + kvb + (size_t)(64 + key) * HD + d8 * 8);
    }
    #pragma unroll
    for (int p = 0; p < 4; p++) {
        int idx = tid + p * 128;
        int d = idx >> 3, k8 = idx & 7;
        cp16(sb + (uint32_t)(AVSB(1) + d * 144 + k8 * 16),
             Vt + kvb + (size_t)d * N_ + 64 + k8 * 8);
    }
    CPCOMMIT();
    if (tid < 64) ms[64 + tid] = mask[b * N_ + 64 + tid] ? 0.0f : -10000.0f;

    float of[2][8][4] = {};
    float mx[4] = {-1e30f, -1e30f, -1e30f, -1e30f};
    float lsum[4] = {};
    float sacc[2][8][4];

    // ---- QK(0) ----
    {
        uint32_t kb = sb + (uint32_t)AKSB(0) + ofB;
        #pragma unroll
        for (int mf = 0; mf < 2; mf++)
            #pragma unroll
            for (int nf = 0; nf < 8; nf++)
                #pragma unroll
                for (int e = 0; e < 4; e++) sacc[mf][nf][e] = 0.0f;
        #pragma unroll
        for (int ks = 0; ks < 4; ks++) {
            #pragma unroll
            for (int p = 0; p < 4; p++) {
                uint32_t b0, b1, b2, b3;
                ldsm4(b0, b1, b2, b3, kb + (uint32_t)(p * 2304 + ks * 32));
                #pragma unroll
                for (int mf = 0; mf < 2; mf++) {
                    mma_f16(sacc[mf][2*p],   qf[mf][ks][0], qf[mf][ks][1],
                            qf[mf][ks][2], qf[mf][ks][3], b0, b1);
                    mma_f16(sacc[mf][2*p+1], qf[mf][ks][0], qf[mf][ks][1],
                            qf[mf][ks][2], qf[mf][ks][3], b2, b3);
                }
            }
        }
    }

    // ---- softmax + P-store macro-block (tile index parity selects mask buf) ----
    #define SOFTMAX_PSTORE(MSOFF)                                                   \
    {                                                                               \
        const float* msp = ms + (MSOFF);                                            \
        _Pragma("unroll")                                                           \
        for (int mf = 0; mf < 2; mf++) {                                            \
            float t0 = -1e30f, t1 = -1e30f;                                         \
            _Pragma("unroll")                                                       \
            for (int nf = 0; nf < 8; nf++) {                                        \
                float ma = msp[nf * 8 + 2 * c], mb = msp[nf * 8 + 2 * c + 1];       \
                sacc[mf][nf][0] += ma; sacc[mf][nf][1] += mb;                       \
                sacc[mf][nf][2] += ma; sacc[mf][nf][3] += mb;                       \
                t0 = fmaxf(t0, fmaxf(sacc[mf][nf][0], sacc[mf][nf][1]));            \
                t1 = fmaxf(t1, fmaxf(sacc[mf][nf][2], sacc[mf][nf][3]));            \
            }                                                                       \
            t0 = fmaxf(t0, __shfl_xor_sync(~0u, t0, 1));                            \
            t0 = fmaxf(t0, __shfl_xor_sync(~0u, t0, 2));                            \
            t1 = fmaxf(t1, __shfl_xor_sync(~0u, t1, 1));                            \
            t1 = fmaxf(t1, __shfl_xor_sync(~0u, t1, 2));                            \
            float mn0 = fmaxf(mx[mf*2],   t0);                                      \
            float mn1 = fmaxf(mx[mf*2+1], t1);                                      \
            if (mn0 > mx[mf*2] || mn1 > mx[mf*2+1]) {                               \
                float co0 = __expf(mx[mf*2] - mn0), co1 = __expf(mx[mf*2+1] - mn1); \
                lsum[mf*2] *= co0; lsum[mf*2+1] *= co1;                             \
                _Pragma("unroll")                                                   \
                for (int nf = 0; nf < 8; nf++) {                                    \
                    of[mf][nf][0] *= co0; of[mf][nf][1] *= co0;                     \
                    of[mf][nf][2] *= co1; of[mf][nf][3] *= co1;                     \
                }                                                                   \
                mx[mf*2] = mn0; mx[mf*2+1] = mn1;                                   \
            }                                                                       \
            int rl = 16 * mf + g;                                                   \
            uint32_t* pr0 = (uint32_t*)(smc + APSB + wid * 4608 + rl * 144);        \
            uint32_t* pr1 = (uint32_t*)(smc + APSB + wid * 4608 + (rl + 8) * 144);  \
            _Pragma("unroll")                                                       \
            for (int nf = 0; nf < 8; nf++) {                                        \
                float p0 = __expf(sacc[mf][nf][0] - mx[mf*2]);                      \
                float p1 = __expf(sacc[mf][nf][1] - mx[mf*2]);                      \
                float p2 = __expf(sacc[mf][nf][2] - mx[mf*2+1]);                    \
                float p3 = __expf(sacc[mf][nf][3] - mx[mf*2+1]);                    \
                lsum[mf*2]   += p0 + p1;                                            \
                lsum[mf*2+1] += p2 + p3;                                            \
                __half2 h0 = __floats2half2_rn(p0, p1);                             \
                __half2 h1 = __floats2half2_rn(p2, p3);                             \
                pr0[nf * 4 + c] = *reinterpret_cast<uint32_t*>(&h0);                \
                pr1[nf * 4 + c] = *reinterpret_cast<uint32_t*>(&h1);                \
            }                                                                       \
        }                                                                           \
    }

    SOFTMAX_PSTORE(0)   // tile 0

    for (int t = 0; t < 31; t++) {
        int buf = t & 1, nbuf = buf ^ 1;
        CPWAIT0();
        __syncthreads();   // tile t+1 ready; P(t) stores visible to own warp

        // ---- fused: PV(t) (of) interleaved with QK(t+1) (ns -> sacc) ----
        uint32_t vb = sb + (uint32_t)AVSB(buf)  + ofB;
        uint32_t kb = sb + (uint32_t)AKSB(nbuf) + ofB;
        #pragma unroll
        for (int mf = 0; mf < 2; mf++)
            #pragma unroll
            for (int nf = 0; nf < 8; nf++)
                #pragma unroll
                for (int e = 0; e < 4; e++) sacc[mf][nf][e] = 0.0f;
        #pragma unroll
        for (int ks = 0; ks < 4; ks++) {
            uint32_t a[2][4];
            ldsm4(a[0][0], a[0][1], a[0][2], a[0][3], pbase + (uint32_t)(ks * 32));
            ldsm4(a[1][0], a[1][1], a[1][2], a[1][3],
                  pbase + (uint32_t)(16 * 144 + ks * 32));
            #pragma unroll
            for (int p = 0; p < 4; p++) {
                uint32_t b0, b1, b2, b3;
                ldsm4(b0, b1, b2, b3, vb + (uint32_t)(p * 2304 + ks * 32));
                uint32_t k0, k1, k2, k3;
                ldsm4(k0, k1, k2, k3, kb + (uint32_t)(p * 2304 + ks * 32));
                #pragma unroll
                for (int mf = 0; mf < 2; mf++) {
                    mma_f16(of[mf][2*p],   a[mf][0], a[mf][1], a[mf][2], a[mf][3], b0, b1);
                    mma_f16(sacc[mf][2*p], qf[mf][ks][0], qf[mf][ks][1],
                            qf[mf][ks][2], qf[mf][ks][3], k0, k1);
                    mma_f16(of[mf][2*p+1],   a[mf][0], a[mf][1], a[mf][2], a[mf][3], b2, b3);
                    mma_f16(sacc[mf][2*p+1], qf[mf][ks][0], qf[mf][ks][1],
                            qf[mf][ks][2], qf[mf][ks][3], k2, k3);
                }
            }
        }
        __syncthreads();   // Vs(buf)/Ks(buf) fully consumed

        if (t < 30) {
            int kn = (t + 2) * 64;
            #pragma unroll
            for (int p = 0; p < 4; p++) {
                int idx = tid + p * 128;
                int key = idx >> 3, d8 = idx & 7;
                cp16(sb + (uint32_t)(AKSB(buf) + key * 144 + d8 * 16),
                     K + kvb + (size_t)(kn + key) * HD + d8 * 8);
            }
            #pragma unroll
            for (int p = 0; p < 4; p++) {
                int idx = tid + p * 128;
                int d = idx >> 3, k8 = idx & 7;
                cp16(sb + (uint32_t)(AVSB(buf) + d * 144 + k8 * 16),
                     Vt + kvb + (size_t)d * N_ + kn + k8 * 8);
            }
            CPCOMMIT();
            if (tid < 64)
                ms[buf * 64 + tid] = mask[b * N_ + kn + tid] ? 0.0f : -10000.0f;
        }

        // softmax(t+1) + P-store(t+1)
        SOFTMAX_PSTORE(nbuf * 64)
    }

    // ---- epilogue: PV(31) ----
    __syncwarp();
    {
        uint32_t vb = sb + (uint32_t)AVSB(1) + ofB;
        #pragma unroll
        for (int ks = 0; ks < 4; ks++) {
            uint32_t a[2][4];
            ldsm4(a[0][0], a[0][1], a[0][2], a[0][3], pbase + (uint32_t)(ks * 32));
            ldsm4(a[1][0], a[1][1], a[1][2], a[1][3],
                  pbase + (uint32_t)(16 * 144 + ks * 32));
            #pragma unroll
            for (int p = 0; p < 4; p++) {
                uint32_t b0, b1, b2, b3;
                ldsm4(b0, b1, b2, b3, vb + (uint32_t)(p * 2304 + ks * 32));
                #pragma unroll
                for (int mf = 0; mf < 2; mf++) {
                    mma_f16(of[mf][2*p],   a[mf][0], a[mf][1], a[mf][2], a[mf][3], b0, b1);
                    mma_f16(of[mf][2*p+1], a[mf][0], a[mf][1], a[mf][2], a[mf][3], b2, b3);
                }
            }
        }
    }

    #pragma unroll
    for (int i = 0; i < 4; i++) {
        lsum[i] += __shfl_xor_sync(~0u, lsum[i], 1);
        lsum[i] += __shfl_xor_sync(~0u, lsum[i], 2);
    }
    #pragma unroll
    for (int mf = 0; mf < 2; mf++) {
        float inv0 = 1.0f / lsum[mf*2], inv1 = 1.0f / lsum[mf*2+1];
        __half* Op = O + ((size_t)bh * N_ + r0 + 16 * mf) * HD;
        #pragma unroll
        for (int nf = 0; nf < 8; nf++) {
            int d = nf * 8 + 2 * c;
            __half2 h0 = __floats2half2_rn(of[mf][nf][0] * inv0, of[mf][nf][1] * inv0);
            __half2 h1 = __floats2half2_rn(of[mf][nf][2] * inv1, of[mf][nf][3] * inv1);
            *reinterpret_cast<__half2*>(Op + d) = h0;
            *reinterpret_cast<__half2*>(Op + 8 * HD + d) = h1;
        }
    }
}

// ---------------- Output projection (round-13 verified) -------------------------
__global__ __launch_bounds__(128) void out_gemm(
    const __half* __restrict__ AO, const float* __restrict__ bias, float* __restrict__ out)
{
    __shared__ __align__(16) char sAc[2 * 9216];
    __shared__ __align__(16) char sBc[2 * 9216];
    uint32_t aB = (uint32_t)__cvta_generic_to_shared(sAc);
    uint32_t bB = (uint32_t)__cvta_generic_to_shared(sBc);
    const __half* Wt = &g_wt[3][0];

    int tid = threadIdx.x, lane = tid & 31, wid = tid >> 5;
    int wM = wid >> 1, wN = wid & 1, g = lane >> 2, c = lane & 3;
    int rowbase = blockIdx.y * 64, colbase = blockIdx.x * 64;
    int bb = rowbase >> 11, nbase = rowbase & (N_ - 1);

    int sel = lane >> 3, l8 = lane & 7;
    uint32_t ofA = (uint32_t)(((sel & 1) * 8 + l8) * 144 + (sel >> 1) * 16);
    uint32_t ofB = (uint32_t)(((sel >> 1) * 8 + l8) * 144 + (sel & 1) * 16);

    #pragma unroll
    for (int p = 0; p < 4; p++) {
        int idx = tid + p * 128;
        int r = idx >> 3, d8 = idx & 7;
        uint32_t off = (uint32_t)(r * 144 + d8 * 16);
        cp16(aB + off, AO + (((size_t)bb * H_ + 0) * N_ + nbase + r) * HD + d8 * 8);
        cp16(bB + off, Wt + (size_t)(colbase + r) * C_ + d8 * 8);
    }
    CPCOMMIT();

    float acc[2][4][4] = {};
    for (int t = 0; t < 8; t++) {
        int buf = t & 1;
        CPWAIT0();
        __syncthreads();
        if (t < 7) {
            int h = t + 1, k0 = (t + 1) * 64;
            uint32_t bo = (uint32_t)((buf ^ 1) * 9216);
            #pragma unroll
            for (int p = 0; p < 4; p++) {
                int idx = tid + p * 128;
                int r = idx >> 3, d8 = idx & 7;
                uint32_t off = bo + (uint32_t)(r * 144 + d8 * 16);
                cp16(aB + off, AO + (((size_t)bb * H_ + h) * N_ + nbase + r) * HD + d8 * 8);
                cp16(bB + off, Wt + (size_t)(colbase + r) * C_ + k0 + d8 * 8);
            }
            CPCOMMIT();
        }
        gemm_frag_f16(aB, bB, buf, wM, wN, ofA, ofB, acc);
    }

    #pragma unroll
    for (int mf = 0; mf < 2; mf++) {
        int r = rowbase + wM * 32 + mf * 16 + g;
        #pragma unroll
        for (int nf = 0; nf < 4; nf++) {
            int cc = colbase + wN * 32 + nf * 8 + 2 * c;
            float b0 = bias[cc], b1 = bias[cc + 1];
            *reinterpret_cast<float2*>(out + (size_t)r * C_ + cc) =
                make_float2(acc[mf][nf][0] + b0, acc[mf][nf][1] + b1);
            *reinterpret_cast<float2*>(out + (size_t)(r + 8) * C_ + cc) =
                make_float2(acc[mf][nf][2] + b0, acc[mf][nf][3] + b1);
        }
    }
}

// ---------------- launch ----------------------------------------------------------
extern "C" void kernel_launch(void* const* d_in, const int* in_sizes, int n_in,
                              void* d_out, int out_size)
{
    const float* x    = (const float*)d_in[0];
    const int*   mask = (const int*)  d_in[1];
    const float* ln_g = (const float*)d_in[2];
    const float* ln_b = (const float*)d_in[3];
    const float* wq   = (const float*)d_in[4];
    const float* bq   = (const float*)d_in[5];
    const float* wk   = (const float*)d_in[6];
    const float* bk   = (const float*)d_in[7];
    const float* wv   = (const float*)d_in[8];
    const float* bv   = (const float*)d_in[9];
    const float* wo   = (const float*)d_in[10];
    const float* bo   = (const float*)d_in[11];
    float* out = (float*)d_out;

    __half *xn, *q, *k, *v, *ao;
    cudaGetSymbolAddress((void**)&xn, g_xn);
    cudaGetSymbolAddress((void**)&q,  g_q);
    cudaGetSymbolAddress((void**)&k,  g_k);
    cudaGetSymbolAddress((void**)&v,  g_v);
    cudaGetSymbolAddress((void**)&ao, g_ao);

    cudaFuncSetAttribute(attn_t, cudaFuncAttributeMaxDynamicSharedMemorySize, ATTN_SMB);

    prep_w<<<dim3(16, 16, 4), 256>>>(wq, wk, wv, wo);
    ln_kernel<<<BN_, 128>>>(x, ln_g, ln_b, xn);
    qkv_gemm<<<dim3(C_ / 64, BN_ / 64, 3), 128>>>(xn, bq, bk, bv, q, k, v);
    attn_t<<<dim3(N_ / 128, BH_), 128, ATTN_SMB>>>(q, k, v, mask, ao);
    out_gemm<<<dim3(C_ / 64, BN_ / 64), 128>>>(ao, bo, out);
}

// round 15
// speedup vs baseline: 1.0673x; 1.0673x over previous
#include <cuda_runtime.h>
#include <cuda_fp16.h>
#include <stdint.h>

#define B_  2
#define N_  2048
#define C_  512
#define H_  8
#define HD  64
#define BN_ (B_*N_)
#define BH_ (B_*H_)
#define SCALE 0.04419417382415922f

__device__ __half g_xn[(size_t)BN_ * C_];
__device__ __half g_q [(size_t)BH_ * N_ * HD];
__device__ __half g_k [(size_t)BH_ * N_ * HD];
__device__ __half g_v [(size_t)BH_ * N_ * HD];   // [b,h,d,n] transposed
__device__ __half g_ao[(size_t)BH_ * N_ * HD];
__device__ __half g_wt[4][(size_t)C_ * C_];      // transposed [n][k]

__device__ __forceinline__ void mma_f16(float c[4],
    uint32_t a0, uint32_t a1, uint32_t a2, uint32_t a3, uint32_t b0, uint32_t b1)
{
    asm volatile(
        "mma.sync.aligned.m16n8k16.row.col.f32.f16.f16.f32 "
        "{%0,%1,%2,%3}, {%4,%5,%6,%7}, {%8,%9}, {%0,%1,%2,%3};"
        : "+f"(c[0]), "+f"(c[1]), "+f"(c[2]), "+f"(c[3])
        : "r"(a0), "r"(a1), "r"(a2), "r"(a3), "r"(b0), "r"(b1));
}
__device__ __forceinline__ void ldsm4(uint32_t& r0, uint32_t& r1, uint32_t& r2,
                                      uint32_t& r3, uint32_t a)
{
    asm volatile("ldmatrix.sync.aligned.m8n8.x4.shared.b16 {%0,%1,%2,%3}, [%4];"
        : "=r"(r0), "=r"(r1), "=r"(r2), "=r"(r3) : "r"(a));
}
__device__ __forceinline__ void cp16(uint32_t dst, const void* src) {
    asm volatile("cp.async.cg.shared.global [%0], [%1], 16;" :: "r"(dst), "l"(src));
}
#define CPCOMMIT() asm volatile("cp.async.commit_group;")
#define CPWAIT0()  asm volatile("cp.async.wait_group 0;")

// ---------------- fused prep: weight transpose (blocks 0-1023) + LN (rest) -----
__global__ __launch_bounds__(256) void prep_fused(
    const float* __restrict__ wq, const float* __restrict__ wk,
    const float* __restrict__ wv, const float* __restrict__ wo,
    const float* __restrict__ x,  const float* __restrict__ lg,
    const float* __restrict__ lb, __half* __restrict__ xn)
{
    int bid = blockIdx.x;
    if (bid < 1024) {
        __shared__ float tile[32][33];
        int m = bid >> 8, b8 = bid & 255;
        const float* s = (m == 0) ? wq : (m == 1) ? wk : (m == 2) ? wv : wo;
        int x0 = (b8 & 15) * 32, y0 = (b8 >> 4) * 32;
        int tx = threadIdx.x & 31, ty = threadIdx.x >> 5;
        #pragma unroll
        for (int i = 0; i < 4; i++)
            tile[ty + 8 * i][tx] = s[(size_t)(y0 + ty + 8 * i) * C_ + x0 + tx];
        __syncthreads();
        #pragma unroll
        for (int i = 0; i < 4; i++)
            g_wt[m][(size_t)(x0 + ty + 8 * i) * C_ + y0 + tx] =
                __float2half_rn(tile[tx][ty + 8 * i]);
    } else {
        // LN: two rows per block; threads 0-127 -> row r0, 128-255 -> row r0+1
        __shared__ float sh[2][8];
        int half_ = threadIdx.x >> 7;
        int tid = threadIdx.x & 127;
        int row = (bid - 1024) * 2 + half_;
        float4 v = reinterpret_cast<const float4*>(x + (size_t)row * C_)[tid];
        float s = v.x + v.y + v.z + v.w;
        float ss = v.x*v.x + v.y*v.y + v.z*v.z + v.w*v.w;
        #pragma unroll
        for (int o = 16; o; o >>= 1) {
            s  += __shfl_xor_sync(~0u, s,  o);
            ss += __shfl_xor_sync(~0u, ss, o);
        }
        int w = tid >> 5, l = tid & 31;
        if (l == 0) { sh[half_][w] = s; sh[half_][4 + w] = ss; }
        __syncthreads();
        float st  = sh[half_][0] + sh[half_][1] + sh[half_][2] + sh[half_][3];
        float sst = sh[half_][4] + sh[half_][5] + sh[half_][6] + sh[half_][7];
        float mean = st * (1.0f / C_);
        float var  = sst * (1.0f / C_) - mean * mean;
        float r = rsqrtf(var + 1e-5f);
        float4 gg = reinterpret_cast<const float4*>(lg)[tid];
        float4 bb = reinterpret_cast<const float4*>(lb)[tid];
        __half2 h0 = __floats2half2_rn((v.x - mean) * r * gg.x + bb.x,
                                       (v.y - mean) * r * gg.y + bb.y);
        __half2 h1 = __floats2half2_rn((v.z - mean) * r * gg.z + bb.z,
                                       (v.w - mean) * r * gg.w + bb.w);
        uint2 st2 = make_uint2(*reinterpret_cast<uint32_t*>(&h0),
                               *reinterpret_cast<uint32_t*>(&h1));
        *reinterpret_cast<uint2*>(xn + (size_t)row * C_ + tid * 4) = st2;
    }
}

// ============================================================================
// fp16 GEMM (round-13 verified): 64x64 tile, BK=64, 128 thr, stride-144 smem.
// ============================================================================
__device__ __forceinline__ void gemm_frag_f16(
    uint32_t aBase, uint32_t bBase, int buf, int wM, int wN,
    uint32_t ofA, uint32_t ofB, float acc[2][4][4])
{
    #pragma unroll
    for (int ks = 0; ks < 4; ks++) {
        uint32_t a[2][4];
        #pragma unroll
        for (int mf = 0; mf < 2; mf++)
            ldsm4(a[mf][0], a[mf][1], a[mf][2], a[mf][3],
                  aBase + (uint32_t)(buf * 9216 + (wM * 32 + mf * 16) * 144 + ks * 32) + ofA);
        #pragma unroll
        for (int p = 0; p < 2; p++) {
            uint32_t b0, b1, b2, b3;
            ldsm4(b0, b1, b2, b3,
                  bBase + (uint32_t)(buf * 9216 + (wN * 32 + p * 16) * 144 + ks * 32) + ofB);
            #pragma unroll
            for (int mf = 0; mf < 2; mf++) {
                mma_f16(acc[mf][2*p],   a[mf][0], a[mf][1], a[mf][2], a[mf][3], b0, b1);
                mma_f16(acc[mf][2*p+1], a[mf][0], a[mf][1], a[mf][2], a[mf][3], b2, b3);
            }
        }
    }
}

__global__ __launch_bounds__(128) void qkv_gemm(
    const __half* __restrict__ A,
    const float* __restrict__ bq, const float* __restrict__ bk, const float* __restrict__ bv,
    __half* __restrict__ Q, __half* __restrict__ K, __half* __restrict__ V)
{
    __shared__ __align__(16) char sAc[2 * 9216];
    __shared__ __align__(16) char sBc[2 * 9216];
    uint32_t aB = (uint32_t)__cvta_generic_to_shared(sAc);
    uint32_t bB = (uint32_t)__cvta_generic_to_shared(sBc);

    int z = blockIdx.z;
    const __half* Wt = &g_wt[z][0];
    const float* bias = (z == 0) ? bq : (z == 1) ? bk : bv;

    int tid = threadIdx.x, lane = tid & 31, wid = tid >> 5;
    int wM = wid >> 1, wN = wid & 1, g = lane >> 2, c = lane & 3;
    int rowbase = blockIdx.y * 64, colbase = blockIdx.x * 64;

    int sel = lane >> 3, l8 = lane & 7;
    uint32_t ofA = (uint32_t)(((sel & 1) * 8 + l8) * 144 + (sel >> 1) * 16);
    uint32_t ofB = (uint32_t)(((sel >> 1) * 8 + l8) * 144 + (sel & 1) * 16);

    #pragma unroll
    for (int p = 0; p < 4; p++) {
        int idx = tid + p * 128;
        int r = idx >> 3, k8 = idx & 7;
        uint32_t off = (uint32_t)(r * 144 + k8 * 16);
        cp16(aB + off, A  + (size_t)(rowbase + r) * C_ + k8 * 8);
        cp16(bB + off, Wt + (size_t)(colbase + r) * C_ + k8 * 8);
    }
    CPCOMMIT();

    float acc[2][4][4] = {};
    for (int t = 0; t < 8; t++) {
        int buf = t & 1;
        CPWAIT0();
        __syncthreads();
        if (t < 7) {
            int k0 = (t + 1) * 64;
            uint32_t bo = (uint32_t)((buf ^ 1) * 9216);
            #pragma unroll
            for (int p = 0; p < 4; p++) {
                int idx = tid + p * 128;
                int r = idx >> 3, k8 = idx & 7;
                uint32_t off = bo + (uint32_t)(r * 144 + k8 * 16);
                cp16(aB + off, A  + (size_t)(rowbase + r) * C_ + k0 + k8 * 8);
                cp16(bB + off, Wt + (size_t)(colbase + r) * C_ + k0 + k8 * 8);
            }
            CPCOMMIT();
        }
        gemm_frag_f16(aB, bB, buf, wM, wN, ofA, ofB, acc);
    }

    int h = blockIdx.x;
    int bb = rowbase >> 11, nbase = rowbase & (N_ - 1);
    if (z != 2) {
        __half* out = z ? K : Q;
        float sc = z ? 1.0f : SCALE;
        #pragma unroll
        for (int mf = 0; mf < 2; mf++) {
            int rl = wM * 32 + mf * 16 + g;
            #pragma unroll
            for (int nf = 0; nf < 4; nf++) {
                int d = wN * 32 + nf * 8 + 2 * c;
                float b0 = bias[colbase + d], b1 = bias[colbase + d + 1];
                __half2 h0 = __floats2half2_rn((acc[mf][nf][0] + b0) * sc,
                                               (acc[mf][nf][1] + b1) * sc);
                __half2 h1 = __floats2half2_rn((acc[mf][nf][2] + b0) * sc,
                                               (acc[mf][nf][3] + b1) * sc);
                *reinterpret_cast<__half2*>(
                    out + (((size_t)bb * H_ + h) * N_ + nbase + rl) * HD + d) = h0;
                *reinterpret_cast<__half2*>(
                    out + (((size_t)bb * H_ + h) * N_ + nbase + rl + 8) * HD + d) = h1;
            }
        }
    } else {
        __syncthreads();
        float* tb = (float*)sAc;   // [64][65]
        #pragma unroll
        for (int mf = 0; mf < 2; mf++) {
            int rl = wM * 32 + mf * 16 + g;
            #pragma unroll
            for (int nf = 0; nf < 4; nf++) {
                int d = wN * 32 + nf * 8 + 2 * c;
                float b0 = bias[colbase + d], b1 = bias[colbase + d + 1];
                tb[d * 65 + rl]           = acc[mf][nf][0] + b0;
                tb[(d + 1) * 65 + rl]     = acc[mf][nf][1] + b1;
                tb[d * 65 + rl + 8]       = acc[mf][nf][2] + b0;
                tb[(d + 1) * 65 + rl + 8] = acc[mf][nf][3] + b1;
            }
        }
        __syncthreads();
        #pragma unroll
        for (int p = 0; p < 8; p++) {
            int idx = tid + p * 128;
            int d = idx >> 4, n4 = idx & 15;
            __half2 v0 = __floats2half2_rn(tb[d * 65 + n4 * 4],     tb[d * 65 + n4 * 4 + 1]);
            __half2 v1 = __floats2half2_rn(tb[d * 65 + n4 * 4 + 2], tb[d * 65 + n4 * 4 + 3]);
            uint2 st = make_uint2(*reinterpret_cast<uint32_t*>(&v0),
                                  *reinterpret_cast<uint32_t*>(&v1));
            *reinterpret_cast<uint2*>(
                V + (((size_t)bb * H_ + h) * HD + d) * N_ + nbase + n4 * 4) = st;
        }
    }
}

// ============================================================================
// Flash attention fp16 (round-13 verified): 128 q/CTA, 4 warps x 32 q-rows.
// smem bytes: Ks 2*9216, Vs 2*9216, Ps 4*4608, ms 512  -> 55808
// ============================================================================
#define AKSB(buf) ((buf) * 9216)
#define AVSB(buf) (18432 + (buf) * 9216)
#define APSB      36864
#define AMSB      55296
#define ATTN_SMB  55808

__global__ __launch_bounds__(128, 2) void attn_t(
    const __half* __restrict__ Q, const __half* __restrict__ K,
    const __half* __restrict__ Vt, const int* __restrict__ mask,
    __half* __restrict__ O)
{
    extern __shared__ char smc[];
    float* ms = (float*)(smc + AMSB);
    uint32_t sb = (uint32_t)__cvta_generic_to_shared(smc);

    int bh = blockIdx.y, b = bh >> 3;
    int qbase = blockIdx.x * 128;
    int tid = threadIdx.x, wid = tid >> 5, lane = tid & 31;
    int g = lane >> 2, c = lane & 3;
    int r0 = qbase + wid * 32 + g;
    const size_t kvb = (size_t)bh * N_ * HD;

    int sel = lane >> 3, l8 = lane & 7;
    uint32_t ofB = (uint32_t)(((sel >> 1) * 8 + l8) * 144 + (sel & 1) * 16);
    uint32_t ofA = (uint32_t)(((sel & 1) * 8 + l8) * 144 + (sel >> 1) * 16);
    uint32_t pbase = sb + (uint32_t)(APSB + wid * 4608) + ofA;

    uint32_t qf[2][4][4];
    #pragma unroll
    for (int mf = 0; mf < 2; mf++) {
        const uint32_t* Qp = reinterpret_cast<const uint32_t*>(
            Q + ((size_t)bh * N_ + r0 + 16 * mf) * HD);
        #pragma unroll
        for (int ks = 0; ks < 4; ks++) {
            qf[mf][ks][0] = Qp[ks * 8 + c];
            qf[mf][ks][1] = Qp[256 + ks * 8 + c];
            qf[mf][ks][2] = Qp[ks * 8 + 4 + c];
            qf[mf][ks][3] = Qp[256 + ks * 8 + 4 + c];
        }
    }

    #pragma unroll
    for (int p = 0; p < 4; p++) {
        int idx = tid + p * 128;
        int key = idx >> 3, d8 = idx & 7;
        cp16(sb + (uint32_t)(AKSB(0) + key * 144 + d8 * 16),
             K + kvb + (size_t)key * HD + d8 * 8);
    }
    #pragma unroll
    for (int p = 0; p < 4; p++) {
        int idx = tid + p * 128;
        int d = idx >> 3, k8 = idx & 7;
        cp16(sb + (uint32_t)(AVSB(0) + d * 144 + k8 * 16),
             Vt + kvb + (size_t)d * N_ + k8 * 8);
    }
    CPCOMMIT();
    if (tid < 64) ms[tid] = mask[b * N_ + tid] ? 0.0f : -10000.0f;

    float of[2][8][4] = {};
    float mx[4] = {-1e30f, -1e30f, -1e30f, -1e30f};
    float lsum[4] = {};

    for (int t = 0; t < 32; t++) {
        int buf = t & 1;
        CPWAIT0();
        __syncthreads();
        int mreg = 0;
        if (t < 31) {
            int kn = (t + 1) * 64;
            #pragma unroll
            for (int p = 0; p < 4; p++) {
                int idx = tid + p * 128;
                int key = idx >> 3, d8 = idx & 7;
                cp16(sb + (uint32_t)(AKSB(buf ^ 1) + key * 144 + d8 * 16),
                     K + kvb + (size_t)(kn + key) * HD + d8 * 8);
            }
            #pragma unroll
            for (int p = 0; p < 4; p++) {
                int idx = tid + p * 128;
                int d = idx >> 3, k8 = idx & 7;
                cp16(sb + (uint32_t)(AVSB(buf ^ 1) + d * 144 + k8 * 16),
                     Vt + kvb + (size_t)d * N_ + kn + k8 * 8);
            }
            CPCOMMIT();
            if (tid < 64) mreg = mask[b * N_ + kn + tid];
        }

        uint32_t kb = sb + (uint32_t)AKSB(buf) + ofB;
        float sacc[2][8][4] = {};
        #pragma unroll
        for (int ks = 0; ks < 4; ks++) {
            #pragma unroll
            for (int p = 0; p < 4; p++) {
                uint32_t b0, b1, b2, b3;
                ldsm4(b0, b1, b2, b3, kb + (uint32_t)(p * 2304 + ks * 32));
                #pragma unroll
                for (int mf = 0; mf < 2; mf++) {
                    mma_f16(sacc[mf][2*p],   qf[mf][ks][0], qf[mf][ks][1],
                            qf[mf][ks][2], qf[mf][ks][3], b0, b1);
                    mma_f16(sacc[mf][2*p+1], qf[mf][ks][0], qf[mf][ks][1],
                            qf[mf][ks][2], qf[mf][ks][3], b2, b3);
                }
            }
        }

        const float* msp = ms + buf * 64;
        #pragma unroll
        for (int mf = 0; mf < 2; mf++) {
            float t0 = -1e30f, t1 = -1e30f;
            #pragma unroll
            for (int nf = 0; nf < 8; nf++) {
                float ma = msp[nf * 8 + 2 * c], mb = msp[nf * 8 + 2 * c + 1];
                sacc[mf][nf][0] += ma; sacc[mf][nf][1] += mb;
                sacc[mf][nf][2] += ma; sacc[mf][nf][3] += mb;
                t0 = fmaxf(t0, fmaxf(sacc[mf][nf][0], sacc[mf][nf][1]));
                t1 = fmaxf(t1, fmaxf(sacc[mf][nf][2], sacc[mf][nf][3]));
            }
            t0 = fmaxf(t0, __shfl_xor_sync(~0u, t0, 1));
            t0 = fmaxf(t0, __shfl_xor_sync(~0u, t0, 2));
            t1 = fmaxf(t1, __shfl_xor_sync(~0u, t1, 1));
            t1 = fmaxf(t1, __shfl_xor_sync(~0u, t1, 2));
            float mn0 = fmaxf(mx[mf*2],   t0);
            float mn1 = fmaxf(mx[mf*2+1], t1);
            if (mn0 > mx[mf*2] || mn1 > mx[mf*2+1]) {
                float co0 = __expf(mx[mf*2] - mn0), co1 = __expf(mx[mf*2+1] - mn1);
                lsum[mf*2] *= co0; lsum[mf*2+1] *= co1;
                #pragma unroll
                for (int nf = 0; nf < 8; nf++) {
                    of[mf][nf][0] *= co0; of[mf][nf][1] *= co0;
                    of[mf][nf][2] *= co1; of[mf][nf][3] *= co1;
                }
                mx[mf*2] = mn0; mx[mf*2+1] = mn1;
            }
        }

        #pragma unroll
        for (int mf = 0; mf < 2; mf++) {
            int rl = 16 * mf + g;
            uint32_t* pr0 = (uint32_t*)(smc + APSB + wid * 4608 + rl * 144);
            uint32_t* pr1 = (uint32_t*)(smc + APSB + wid * 4608 + (rl + 8) * 144);
            #pragma unroll
            for (int nf = 0; nf < 8; nf++) {
                float p0 = __expf(sacc[mf][nf][0] - mx[mf*2]);
                float p1 = __expf(sacc[mf][nf][1] - mx[mf*2]);
                float p2 = __expf(sacc[mf][nf][2] - mx[mf*2+1]);
                float p3 = __expf(sacc[mf][nf][3] - mx[mf*2+1]);
                lsum[mf*2]   += p0 + p1;
                lsum[mf*2+1] += p2 + p3;
                __half2 h0 = __floats2half2_rn(p0, p1);
                __half2 h1 = __floats2half2_rn(p2, p3);
                pr0[nf * 4 + c] = *reinterpret_cast<uint32_t*>(&h0);
                pr1[nf * 4 + c] = *reinterpret_cast<uint32_t*>(&h1);
            }
        }
        __syncwarp();

        uint32_t vb = sb + (uint32_t)AVSB(buf) + ofB;
        #pragma unroll
        for (int ks = 0; ks < 4; ks++) {
            uint32_t a[2][4];
            ldsm4(a[0][0], a[0][1], a[0][2], a[0][3], pbase + (uint32_t)(ks * 32));
            ldsm4(a[1][0], a[1][1], a[1][2], a[1][3],
                  pbase + (uint32_t)(16 * 144 + ks * 32));
            #pragma unroll
            for (int p = 0; p < 4; p++) {
                uint32_t b0, b1, b2, b3;
                ldsm4(b0, b1, b2, b3, vb + (uint32_t)(p * 2304 + ks * 32));
                #pragma unroll
                for (int mf = 0; mf < 2; mf++) {
                    mma_f16(of[mf][2*p],   a[mf][0], a[mf][1], a[mf][2], a[mf][3], b0, b1);
                    mma_f16(of[mf][2*p+1], a[mf][0], a[mf][1], a[mf][2], a[mf][3], b2, b3);
                }
            }
        }
        if (t < 31 && tid < 64)
            ms[(buf ^ 1) * 64 + tid] = mreg ? 0.0f : -10000.0f;
    }

    #pragma unroll
    for (int i = 0; i < 4; i++) {
        lsum[i] += __shfl_xor_sync(~0u, lsum[i], 1);
        lsum[i] += __shfl_xor_sync(~0u, lsum[i], 2);
    }
    #pragma unroll
    for (int mf = 0; mf < 2; mf++) {
        float inv0 = 1.0f / lsum[mf*2], inv1 = 1.0f / lsum[mf*2+1];
        __half* Op = O + ((size_t)bh * N_ + r0 + 16 * mf) * HD;
        #pragma unroll
        for (int nf = 0; nf < 8; nf++) {
            int d = nf * 8 + 2 * c;
            __half2 h0 = __floats2half2_rn(of[mf][nf][0] * inv0, of[mf][nf][1] * inv0);
            __half2 h1 = __floats2half2_rn(of[mf][nf][2] * inv1, of[mf][nf][3] * inv1);
            *reinterpret_cast<__half2*>(Op + d) = h0;
            *reinterpret_cast<__half2*>(Op + 8 * HD + d) = h1;
        }
    }
}

// ---------------- Output projection (round-13 verified) -------------------------
__global__ __launch_bounds__(128) void out_gemm(
    const __half* __restrict__ AO, const float* __restrict__ bias, float* __restrict__ out)
{
    __shared__ __align__(16) char sAc[2 * 9216];
    __shared__ __align__(16) char sBc[2 * 9216];
    uint32_t aB = (uint32_t)__cvta_generic_to_shared(sAc);
    uint32_t bB = (uint32_t)__cvta_generic_to_shared(sBc);
    const __half* Wt = &g_wt[3][0];

    int tid = threadIdx.x, lane = tid & 31, wid = tid >> 5;
    int wM = wid >> 1, wN = wid & 1, g = lane >> 2, c = lane & 3;
    int rowbase = blockIdx.y * 64, colbase = blockIdx.x * 64;
    int bb = rowbase >> 11, nbase = rowbase & (N_ - 1);

    int sel = lane >> 3, l8 = lane & 7;
    uint32_t ofA = (uint32_t)(((sel & 1) * 8 + l8) * 144 + (sel >> 1) * 16);
    uint32_t ofB = (uint32_t)(((sel >> 1) * 8 + l8) * 144 + (sel & 1) * 16);

    #pragma unroll
    for (int p = 0; p < 4; p++) {
        int idx = tid + p * 128;
        int r = idx >> 3, d8 = idx & 7;
        uint32_t off = (uint32_t)(r * 144 + d8 * 16);
        cp16(aB + off, AO + (((size_t)bb * H_ + 0) * N_ + nbase + r) * HD + d8 * 8);
        cp16(bB + off, Wt + (size_t)(colbase + r) * C_ + d8 * 8);
    }
    CPCOMMIT();

    float acc[2][4][4] = {};
    for (int t = 0; t < 8; t++) {
        int buf = t & 1;
        CPWAIT0();
        __syncthreads();
        if (t < 7) {
            int h = t + 1, k0 = (t + 1) * 64;
            uint32_t bo = (uint32_t)((buf ^ 1) * 9216);
            #pragma unroll
            for (int p = 0; p < 4; p++) {
                int idx = tid + p * 128;
                int r = idx >> 3, d8 = idx & 7;
                uint32_t off = bo + (uint32_t)(r * 144 + d8 * 16);
                cp16(aB + off, AO + (((size_t)bb * H_ + h) * N_ + nbase + r) * HD + d8 * 8);
                cp16(bB + off, Wt + (size_t)(colbase + r) * C_ + k0 + d8 * 8);
            }
            CPCOMMIT();
        }
        gemm_frag_f16(aB, bB, buf, wM, wN, ofA, ofB, acc);
    }

    #pragma unroll
    for (int mf = 0; mf < 2; mf++) {
        int r = rowbase + wM * 32 + mf * 16 + g;
        #pragma unroll
        for (int nf = 0; nf < 4; nf++) {
            int cc = colbase + wN * 32 + nf * 8 + 2 * c;
            float b0 = bias[cc], b1 = bias[cc + 1];
            *reinterpret_cast<float2*>(out + (size_t)r * C_ + cc) =
                make_float2(acc[mf][nf][0] + b0, acc[mf][nf][1] + b1);
            *reinterpret_cast<float2*>(out + (size_t)(r + 8) * C_ + cc) =
                make_float2(acc[mf][nf][2] + b0, acc[mf][nf][3] + b1);
        }
    }
}

// ---------------- launch ----------------------------------------------------------
extern "C" void kernel_launch(void* const* d_in, const int* in_sizes, int n_in,
                              void* d_out, int out_size)
{
    const float* x    = (const float*)d_in[0];
    const int*   mask = (const int*)  d_in[1];
    const float* ln_g = (const float*)d_in[2];
    const float* ln_b = (const float*)d_in[3];
    const float* wq   = (const float*)d_in[4];
    const float* bq   = (const float*)d_in[5];
    const float* wk   = (const float*)d_in[6];
    const float* bk   = (const float*)d_in[7];
    const float* wv   = (const float*)d_in[8];
    const float* bv   = (const float*)d_in[9];
    const float* wo   = (const float*)d_in[10];
    const float* bo   = (const float*)d_in[11];
    float* out = (float*)d_out;

    __half *xn, *q, *k, *v, *ao;
    cudaGetSymbolAddress((void**)&xn, g_xn);
    cudaGetSymbolAddress((void**)&q,  g_q);
    cudaGetSymbolAddress((void**)&k,  g_k);
    cudaGetSymbolAddress((void**)&v,  g_v);
    cudaGetSymbolAddress((void**)&ao, g_ao);

    cudaFuncSetAttribute(attn_t, cudaFuncAttributeMaxDynamicSharedMemorySize, ATTN_SMB);

    prep_fused<<<1024 + BN_ / 2, 256>>>(wq, wk, wv, wo, x, ln_g, ln_b, xn);
    qkv_gemm<<<dim3(C_ / 64, BN_ / 64, 3), 128>>>(xn, bq, bk, bv, q, k, v);
    attn_t<<<dim3(N_ / 128, BH_), 128, ATTN_SMB>>>(q, k, v, mask, ao);
    out_gemm<<<dim3(C_ / 64, BN_ / 64), 128>>>(ao, bo, out);
}